// round 1
// baseline (speedup 1.0000x reference)
#include <cuda_runtime.h>

#define D 2048
#define D4 (D / 4)
#define THREADS 256
#define NV 2  // float4 chunks per thread per feature: 2048/4/256 = 2

__global__ __launch_bounds__(THREADS, 4) void fc_kernel(
    const float* __restrict__ feat, const float* __restrict__ pos,
    float* __restrict__ out)
{
    const int b = blockIdx.x;
    const int t = threadIdx.x;
    const float4* __restrict__ feat4 = reinterpret_cast<const float4*>(feat);
    const float4* __restrict__ pos4  = reinterpret_cast<const float4*>(pos);
    float4* __restrict__ out4 = reinterpret_cast<float4*>(out);

    const long base = (long)b * 3 * D4;

    float4 f1[NV], f2[NV], f3[NV];
#pragma unroll
    for (int v = 0; v < NV; v++) {
        const int i = t + v * THREADS;
        float4 a  = feat4[base + 0 * D4 + i];
        float4 bb = feat4[base + 1 * D4 + i];
        float4 c  = feat4[base + 2 * D4 + i];
        float4 p0 = __ldg(&pos4[0 * D4 + i]);
        float4 p1 = __ldg(&pos4[1 * D4 + i]);
        float4 p2 = __ldg(&pos4[2 * D4 + i]);
        f1[v] = make_float4(a.x + p0.x, a.y + p0.y, a.z + p0.z, a.w + p0.w);
        f2[v] = make_float4(bb.x + p1.x, bb.y + p1.y, bb.z + p1.z, bb.w + p1.w);
        f3[v] = make_float4(c.x + p2.x, c.y + p2.y, c.z + p2.z, c.w + p2.w);
    }

    // 9 reductions: |f1|^2 |f2|^2 |f3|^2  f1.f2 f1.f3 f2.f3  sum(f1) sum(f2) sum(f3)
    float acc[9];
#pragma unroll
    for (int k = 0; k < 9; k++) acc[k] = 0.0f;

#pragma unroll
    for (int v = 0; v < NV; v++) {
        const float ax[4] = {f1[v].x, f1[v].y, f1[v].z, f1[v].w};
        const float bx[4] = {f2[v].x, f2[v].y, f2[v].z, f2[v].w};
        const float cx[4] = {f3[v].x, f3[v].y, f3[v].z, f3[v].w};
#pragma unroll
        for (int k = 0; k < 4; k++) {
            const float a = ax[k], bq = bx[k], c = cx[k];
            acc[0] = fmaf(a, a, acc[0]);
            acc[1] = fmaf(bq, bq, acc[1]);
            acc[2] = fmaf(c, c, acc[2]);
            acc[3] = fmaf(a, bq, acc[3]);
            acc[4] = fmaf(a, c, acc[4]);
            acc[5] = fmaf(bq, c, acc[5]);
            acc[6] += a;
            acc[7] += bq;
            acc[8] += c;
        }
    }

    // warp reduce
#pragma unroll
    for (int k = 0; k < 9; k++) {
#pragma unroll
        for (int o = 16; o > 0; o >>= 1)
            acc[k] += __shfl_xor_sync(0xffffffffu, acc[k], o);
    }

    __shared__ float sred[9][8];
    __shared__ float alpha[6];
    const int warp = t >> 5, lane = t & 31;
    if (lane == 0) {
#pragma unroll
        for (int k = 0; k < 9; k++) sred[k][warp] = acc[k];
    }
    __syncthreads();

    if (t == 0) {
        float S[9];
#pragma unroll
        for (int k = 0; k < 9; k++) {
            float s = sred[k][0];
#pragma unroll
            for (int w = 1; w < 8; w++) s += sred[k][w];
            S[k] = s;
        }
        const float d11 = S[0], d22 = S[1], d33 = S[2];
        const float d12 = S[3], d13 = S[4], d23 = S[5];
        const float s1 = S[6], s2 = S[7], s3 = S[8];

        const float e   = 1e-6f;
        const float De2 = (float)D * 1e-12f;
        // ||a-b+e||^2 = ||a||^2+||b||^2-2ab + 2e(sa-sb) + D e^2  (direction-dependent)
        const float q12 = d11 + d22 - 2.0f * d12 + De2;
        const float q13 = d11 + d33 - 2.0f * d13 + De2;
        const float q23 = d22 + d33 - 2.0f * d23 + De2;

        const float w12f = 1.0f / (1.0f + sqrtf(fmaxf(q12 + 2.0f * e * (s1 - s2), 0.0f)));
        const float w12b = 1.0f / (1.0f + sqrtf(fmaxf(q12 + 2.0f * e * (s2 - s1), 0.0f)));
        const float w13f = 1.0f / (1.0f + sqrtf(fmaxf(q13 + 2.0f * e * (s1 - s3), 0.0f)));
        const float w13b = 1.0f / (1.0f + sqrtf(fmaxf(q13 + 2.0f * e * (s3 - s1), 0.0f)));
        const float w23f = 1.0f / (1.0f + sqrtf(fmaxf(q23 + 2.0f * e * (s2 - s3), 0.0f)));
        const float w23b = 1.0f / (1.0f + sqrtf(fmaxf(q23 + 2.0f * e * (s3 - s2), 0.0f)));

        const float n1 = fmaxf(sqrtf(d11), 1e-8f);
        const float n2 = fmaxf(sqrtf(d22), 1e-8f);
        const float n3 = fmaxf(sqrtf(d33), 1e-8f);
        const float c12 = 0.5f + 0.5f * d12 / (n1 * n2);
        const float c13 = 0.5f + 0.5f * d13 / (n1 * n3);
        const float c23 = 0.5f + 0.5f * d23 / (n2 * n3);

        alpha[0] = w12f + c12;  // o1 coeff on f2
        alpha[1] = w13f + c13;  // o1 coeff on f3
        alpha[2] = w12b + c12;  // o2 coeff on f1
        alpha[3] = w23f + c23;  // o2 coeff on f3
        alpha[4] = w13b + c13;  // o3 coeff on f1
        alpha[5] = w23b + c23;  // o3 coeff on f2
    }
    __syncthreads();

    const float a12 = alpha[0], a13 = alpha[1];
    const float a21 = alpha[2], a23 = alpha[3];
    const float a31 = alpha[4], a32 = alpha[5];

#pragma unroll
    for (int v = 0; v < NV; v++) {
        const int i = t + v * THREADS;
        float4 o1, o2, o3;
        o1.x = fmaf(a12, f2[v].x, fmaf(a13, f3[v].x, f1[v].x));
        o1.y = fmaf(a12, f2[v].y, fmaf(a13, f3[v].y, f1[v].y));
        o1.z = fmaf(a12, f2[v].z, fmaf(a13, f3[v].z, f1[v].z));
        o1.w = fmaf(a12, f2[v].w, fmaf(a13, f3[v].w, f1[v].w));
        o2.x = fmaf(a21, f1[v].x, fmaf(a23, f3[v].x, f2[v].x));
        o2.y = fmaf(a21, f1[v].y, fmaf(a23, f3[v].y, f2[v].y));
        o2.z = fmaf(a21, f1[v].z, fmaf(a23, f3[v].z, f2[v].z));
        o2.w = fmaf(a21, f1[v].w, fmaf(a23, f3[v].w, f2[v].w));
        o3.x = fmaf(a31, f1[v].x, fmaf(a32, f2[v].x, f3[v].x));
        o3.y = fmaf(a31, f1[v].y, fmaf(a32, f2[v].y, f3[v].y));
        o3.z = fmaf(a31, f1[v].z, fmaf(a32, f2[v].z, f3[v].z));
        o3.w = fmaf(a31, f1[v].w, fmaf(a32, f2[v].w, f3[v].w));
        out4[base + 0 * D4 + i] = o1;
        out4[base + 1 * D4 + i] = o2;
        out4[base + 2 * D4 + i] = o3;
    }
}

extern "C" void kernel_launch(void* const* d_in, const int* in_sizes, int n_in,
                              void* d_out, int out_size) {
    const float* feat = (const float*)d_in[0];
    const float* pos  = (const float*)d_in[1];
    float* out = (float*)d_out;
    const int B = in_sizes[0] / (3 * D);
    fc_kernel<<<B, THREADS>>>(feat, pos, out);
}